// round 12
// baseline (speedup 1.0000x reference)
#include <cuda_runtime.h>
#include <cuda_bf16.h>
#include <stdint.h>

// Problem constants
#define BN 4096
#define CN 1024

typedef unsigned long long u64;
typedef unsigned int u32;

// ---------------- device scratch (no allocations allowed) ----------------
__device__ float g_sq[BN];     // ||x_i||^2
__device__ float g_ce[BN];     // lse_i - x[i,label_i]
__device__ float g_pos[BN];    // dot(x_i, centers[label_i])
__device__ int   g_rand[BN];   // random-negative index
__device__ u64   g_hardkey[BN];// argmax key for hard negative
__device__ u64   g_acc;        // fixed-point (2^30) sum of ce_i + 0.1*info_i
__device__ __nv_bfloat16 g_hi[BN * CN];  // bf16 hi split of outs
__device__ __nv_bfloat16 g_lo[BN * CN];  // bf16 lo split of outs

// ---------------- helpers ----------------
__device__ __forceinline__ uint32_t smem_to_u32(const void* p) {
    uint32_t a;
    asm("{ .reg .u64 t; cvta.to.shared.u64 t, %1; cvt.u32.u64 %0, t; }" : "=r"(a) : "l"(p));
    return a;
}
// 64-byte-row swizzle: XOR 16B-slot bits [5:4] with row bits ((o>>7)&3)
#define SWZ64(o) ((u32)(o) ^ ((((u32)(o)) >> 3) & 0x30u))

__device__ __forceinline__ void ldsm_x4(uint32_t* r, uint32_t addr) {
    asm volatile("ldmatrix.sync.aligned.m8n8.x4.shared.b16 {%0,%1,%2,%3}, [%4];"
        : "=r"(r[0]), "=r"(r[1]), "=r"(r[2]), "=r"(r[3]) : "r"(addr));
}
__device__ __forceinline__ void mma_bf16(float* d, const uint32_t* a, const uint32_t* b) {
    asm volatile("mma.sync.aligned.m16n8k16.row.col.f32.bf16.bf16.f32 "
        "{%0,%1,%2,%3}, {%4,%5,%6,%7}, {%8,%9}, {%0,%1,%2,%3};"
        : "+f"(d[0]), "+f"(d[1]), "+f"(d[2]), "+f"(d[3])
        : "r"(a[0]), "r"(a[1]), "r"(a[2]), "r"(a[3]), "r"(b[0]), "r"(b[1]));
}
__device__ __forceinline__ void cp_async16(uint32_t saddr, const void* g) {
    asm volatile("cp.async.cg.shared.global [%0], [%1], 16;" :: "r"(saddr), "l"(g));
}
#define CP_COMMIT() asm volatile("cp.async.commit_group;" ::: "memory")
#define CP_WAIT1()  asm volatile("cp.async.wait_group 1;" ::: "memory")
#define CP_WAIT0()  asm volatile("cp.async.wait_group 0;" ::: "memory")

// ---------------- threefry2x32 (jax key 42) ----------------
__device__ __forceinline__ void threefry2x32(u32 x0, u32 x1, u32& o0, u32& o1) {
    const u32 ks0 = 0u, ks1 = 42u, ks2 = 0x1BD11BF0u;
    x0 += ks0; x1 += ks1;
#define TFR(r) { x0 += x1; x1 = (x1 << (r)) | (x1 >> (32 - (r))); x1 ^= x0; }
#define TFG0 TFR(13) TFR(15) TFR(26) TFR(6)
#define TFG1 TFR(17) TFR(29) TFR(16) TFR(24)
    TFG0; x0 += ks1; x1 += ks2 + 1u;
    TFG1; x0 += ks2; x1 += ks0 + 2u;
    TFG0; x0 += ks0; x1 += ks1 + 3u;
    TFG1; x0 += ks1; x1 += ks2 + 4u;
    TFG0; x0 += ks2; x1 += ks0 + 5u;
#undef TFR
#undef TFG0
#undef TFG1
    o0 = x0; o1 = x1;
}

// ---------------- K1: per-row stats + bf16 split + hardkey init + acc zero ----------------
__global__ void __launch_bounds__(256) k_rowstats(
    const float* __restrict__ outs,
    const float* __restrict__ centers,
    const int*   __restrict__ label)
{
    int i = blockIdx.x;
    int tid = threadIdx.x;
    int lab = label[i];
    if (tid == 0) {
        g_hardkey[i] = 0ull;
        if (i == 0) g_acc = 0ull;
    }

    __shared__ float s_xlab;
    __shared__ float sm[256];

    float4 x = ((const float4*)(outs + (size_t)i * CN))[tid];
    float4 cc = ((const float4*)(centers + (size_t)lab * CN))[tid];
    float xs[4] = {x.x, x.y, x.z, x.w};
    float cs[4] = {cc.x, cc.y, cc.z, cc.w};
    int c0 = tid * 4;

    float mx = -1e30f, sq = 0.f, pos = 0.f;
    unsigned short h[4], l[4];
#pragma unroll
    for (int k = 0; k < 4; k++) {
        float v = xs[k];
        mx = fmaxf(mx, v);
        sq += v * v;
        pos += v * cs[k];
        if (c0 + k == lab) s_xlab = v;
        __nv_bfloat16 hb = __float2bfloat16(v);
        float hf = __bfloat162float(hb);
        __nv_bfloat16 lb = __float2bfloat16(v - hf);
        h[k] = *reinterpret_cast<unsigned short*>(&hb);
        l[k] = *reinterpret_cast<unsigned short*>(&lb);
    }
    uint2 hv, lv;
    hv.x = (u32)h[0] | ((u32)h[1] << 16); hv.y = (u32)h[2] | ((u32)h[3] << 16);
    lv.x = (u32)l[0] | ((u32)l[1] << 16); lv.y = (u32)l[2] | ((u32)l[3] << 16);
    size_t vidx = ((size_t)i * CN) / 4 + tid;
    ((uint2*)g_hi)[vidx] = hv;
    ((uint2*)g_lo)[vidx] = lv;

    sm[tid] = mx; __syncthreads();
    for (int s = 128; s > 0; s >>= 1) { if (tid < s) sm[tid] = fmaxf(sm[tid], sm[tid + s]); __syncthreads(); }
    float rmax = sm[0]; __syncthreads();
    float se = expf(xs[0] - rmax) + expf(xs[1] - rmax) + expf(xs[2] - rmax) + expf(xs[3] - rmax);
    sm[tid] = se; __syncthreads();
    for (int s = 128; s > 0; s >>= 1) { if (tid < s) sm[tid] += sm[tid + s]; __syncthreads(); }
    float lse = rmax + logf(sm[0]); __syncthreads();
    sm[tid] = sq; __syncthreads();
    for (int s = 128; s > 0; s >>= 1) { if (tid < s) sm[tid] += sm[tid + s]; __syncthreads(); }
    float sqt = sm[0]; __syncthreads();
    sm[tid] = pos; __syncthreads();
    for (int s = 128; s > 0; s >>= 1) { if (tid < s) sm[tid] += sm[tid + s]; __syncthreads(); }
    if (tid == 0) {
        g_sq[i]  = sqt;
        g_pos[i] = sm[0];
        g_ce[i]  = lse - s_xlab;
    }
}

// ---------------- rand-negative block body (runs inside k_hard_mma grid) ----------------
__device__ void rand_block(int i0, const int* __restrict__ label, char* sm) {
    int tid = threadIdx.x;
    int* labs = (int*)sm;                        // 16 KB
    u64* sb0 = (u64*)(sm + BN * 4);              // 2 KB
    u64* sb1 = (u64*)(sm + BN * 4 + 2048);       // 2 KB
    for (int j = tid; j < BN; j += 256) labs[j] = label[j];
    __syncthreads();
    int i1 = i0 + BN / 2;
    int li0 = labs[i0], li1 = labs[i1];
    const u32 HALF = 8388608u;   // (4096*4096)/2

    u64 best0 = 0ull, best1 = 0ull;
    u32 base = (u32)i0 << 12;
    for (int j = tid; j < BN; j += 256) {
        u32 idx = base | (u32)j;
        u32 o0, o1;
        threefry2x32(idx, idx + HALF, o0, o1);
        int lj = labs[j];
        u64 tie = (u64)(0xFFFFFFFFu - (u32)j);
        if (lj != li0) {
            u64 key = ((u64)(o0 >> 9) << 32) | tie;
            if (key > best0) best0 = key;
        }
        if (lj != li1) {
            u64 key = ((u64)(o1 >> 9) << 32) | tie;
            if (key > best1) best1 = key;
        }
    }
    sb0[tid] = best0; sb1[tid] = best1; __syncthreads();
    for (int s = 128; s > 0; s >>= 1) {
        if (tid < s) {
            u64 a = sb0[tid + s]; if (a > sb0[tid]) sb0[tid] = a;
            u64 b = sb1[tid + s]; if (b > sb1[tid]) sb1[tid] = b;
        }
        __syncthreads();
    }
    if (tid == 0) {
        g_rand[i0] = (int)(0xFFFFFFFFu - (u32)(sb0[0] & 0xFFFFFFFFu));
        g_rand[i1] = (int)(0xFFFFFFFFu - (u32)(sb1[0] & 0xFFFFFFFFu));
    }
}

// ---------------- K3: split-bf16 mma.sync GEMM + argmax, interleaved with rand blocks ----
#define KC 32
#define NCHUNK_M (CN / KC)      // 32
#define STAGE_SZ 32768
#define NSTAGE 3
#define OFF_AHI 0
#define OFF_ALO 8192
#define OFF_BHI 16384
#define OFF_BLO 24576
#define OFF_SI  (NSTAGE * STAGE_SZ)     // 98304
#define OFF_SJ  (OFF_SI + 1024)
#define OFF_LA  (OFF_SJ + 1024)
#define OFF_LB  (OFF_LA + 512)
#define OFF_QA  (OFF_LB + 512)
#define OFF_QB  (OFF_QA + 512)
#define HARD_SMEM (OFF_QB + 512)        // 102400
#define NTILES 528                      // 32*33/2
#define GRID_TOTAL (NTILES * 5)         // 2640: 1 mma per 4 rand-ish blocks

__device__ __forceinline__ void prefetch_chunk(uint32_t smem_base, int slot, int c,
                                               int ib, int jb, bool diag, int tid) {
    uint32_t sb = smem_base + (u32)slot * STAGE_SZ;
    int k0 = c * KC;
#pragma unroll
    for (int it = 0; it < 2; it++) {
        int v = tid + it * 256;
        int row = v >> 2, cv = v & 3;
        uint32_t so = SWZ64(row * 64 + cv * 16);
        size_t ga = (size_t)(ib + row) * CN + k0 + cv * 8;
        cp_async16(sb + OFF_AHI + so, g_hi + ga);
        cp_async16(sb + OFF_ALO + so, g_lo + ga);
        if (!diag) {
            size_t gb = (size_t)(jb + row) * CN + k0 + cv * 8;
            cp_async16(sb + OFF_BHI + so, g_hi + gb);
            cp_async16(sb + OFF_BLO + so, g_lo + gb);
        }
    }
    CP_COMMIT();
}

__global__ void __launch_bounds__(256, 2) k_hard_mma(const int* __restrict__ label)
{
    extern __shared__ char sm[];
    uint32_t smem_base = smem_to_u32(sm);
    int tid = threadIdx.x;

    int bid = blockIdx.x;
    if (bid % 5 != 0) {
        // rand block: ordinal r in [0, 2112); first 2048 do work
        int r = bid - bid / 5 - 1;
        if (r < BN / 2) rand_block(r, label, sm);
        return;
    }
    int t = bid / 5;   // mma tile 0..527

    // triangular decode: t -> (bi, bj), bj <= bi
    int bi = (int)((sqrtf(8.0f * (float)t + 1.0f) - 1.0f) * 0.5f);
    while ((bi + 1) * (bi + 2) / 2 <= t) bi++;
    while (bi * (bi + 1) / 2 > t) bi--;
    int bj = t - bi * (bi + 1) / 2;
    int ib = bi * 128, jb = bj * 128;
    bool diag = (bi == bj);
    uint32_t bhiOff = diag ? OFF_AHI : OFF_BHI;
    uint32_t bloOff = diag ? OFF_ALO : OFF_BLO;

    u64* sI = (u64*)(sm + OFF_SI);
    u64* sJ = (u64*)(sm + OFF_SJ);
    int* labA = (int*)(sm + OFF_LA);
    int* labB = (int*)(sm + OFF_LB);
    float* sqA = (float*)(sm + OFF_QA);
    float* sqB = (float*)(sm + OFF_QB);
    if (tid < 128) {
        sI[tid] = 0ull; sJ[tid] = 0ull;
        labA[tid] = label[ib + tid]; sqA[tid] = g_sq[ib + tid];
    } else {
        int u = tid - 128;
        labB[u] = label[jb + u]; sqB[u] = g_sq[jb + u];
    }

    // prologue: stages 0,1
    prefetch_chunk(smem_base, 0, 0, ib, jb, diag, tid);
    prefetch_chunk(smem_base, 1, 1, ib, jb, diag, tid);

    // warp/lane geometry
    int lane = tid & 31, w = tid >> 5;
    int gid = lane >> 2, tig = lane & 3;
    int wm = (w >> 1) * 32;       // 4 warps along m
    int wn = (w & 1) * 64;        // 2 warps along n
    int q  = lane >> 3, i5 = lane & 7;
    int a_r  = i5 + (q & 1) * 8;
    int a_ch = (q >> 1) * 8;
    int b_r  = i5 + (q >> 1) * 8;
    int b_ch = (q & 1) * 8;

    float acc[2][8][4];
#pragma unroll
    for (int m = 0; m < 2; m++)
#pragma unroll
        for (int n = 0; n < 8; n++)
#pragma unroll
            for (int e = 0; e < 4; e++) acc[m][n][e] = 0.f;

    int slot = 0;
    for (int c = 0; c < NCHUNK_M; c++) {
        if (c + 1 < NCHUNK_M) { CP_WAIT1(); } else { CP_WAIT0(); }
        __syncthreads();
        if (c + 2 < NCHUNK_M) {
            int ns = slot + 2; if (ns >= NSTAGE) ns -= NSTAGE;
            prefetch_chunk(smem_base, ns, c + 2, ib, jb, diag, tid);
        }
        uint32_t sb = smem_base + (u32)slot * STAGE_SZ;

#pragma unroll
        for (int ks = 0; ks < 2; ks++) {
            int kc = ks * 16;
            uint32_t ah[2][4], al[2][4];
#pragma unroll
            for (int mt = 0; mt < 2; mt++) {
                uint32_t off = SWZ64((wm + mt * 16 + a_r) * 64 + (kc + a_ch) * 2);
                ldsm_x4(ah[mt], sb + OFF_AHI + off);
                ldsm_x4(al[mt], sb + OFF_ALO + off);
            }
#pragma unroll
            for (int bb = 0; bb < 4; bb++) {
                uint32_t bh[4], bl[4];
                uint32_t off = SWZ64((wn + bb * 16 + b_r) * 64 + (kc + b_ch) * 2);
                ldsm_x4(bh, sb + bhiOff + off);
                ldsm_x4(bl, sb + bloOff + off);
#pragma unroll
                for (int mt = 0; mt < 2; mt++) {
                    mma_bf16(acc[mt][bb * 2],     ah[mt], bh);
                    mma_bf16(acc[mt][bb * 2 + 1], ah[mt], bh + 2);
                    mma_bf16(acc[mt][bb * 2],     ah[mt], bl);
                    mma_bf16(acc[mt][bb * 2 + 1], ah[mt], bl + 2);
                    mma_bf16(acc[mt][bb * 2],     al[mt], bh);
                    mma_bf16(acc[mt][bb * 2 + 1], al[mt], bh + 2);
                }
            }
        }
        slot++; if (slot >= NSTAGE) slot = 0;
    }

    // ---- epilogue: masked argmax, both directions ----
    float bVj[16]; int bJj[16];
#pragma unroll
    for (int x = 0; x < 16; x++) { bVj[x] = -1e38f; bJj[x] = -1; }

#pragma unroll
    for (int mt = 0; mt < 2; mt++) {
#pragma unroll
        for (int h = 0; h < 2; h++) {
            int r = wm + mt * 16 + gid + h * 8;
            int labr = labA[r];
            float sqa = sqA[r];
            float bVi = -1e38f; int bJi = -1;
#pragma unroll
            for (int nt = 0; nt < 8; nt++) {
#pragma unroll
                for (int e = 0; e < 2; e++) {
                    int n = wn + nt * 8 + 2 * tig + e;
                    if (labB[n] != labr) {
                        float m2d = -2.0f * acc[mt][nt][h * 2 + e];
                        float vi = sqB[n] + m2d;
                        int jg = jb + n;
                        if (vi > bVi || (vi == bVi && jg < bJi)) { bVi = vi; bJi = jg; }
                        int ci = nt * 2 + e;
                        float vj = sqa + m2d;
                        int jg2 = ib + r;
                        if (vj > bVj[ci] || (vj == bVj[ci] && jg2 < bJj[ci])) { bVj[ci] = vj; bJj[ci] = jg2; }
                    }
                }
            }
            u64 key = 0ull;
            if (bJi >= 0) {
                u32 fb = __float_as_uint(bVi);
                u32 s = (fb & 0x80000000u) ? ~fb : (fb | 0x80000000u);
                key = ((u64)s << 32) | (u64)(0xFFFFFFFFu - (u32)bJi);
            }
            u64 o1 = __shfl_xor_sync(0xFFFFFFFFu, key, 1); if (o1 > key) key = o1;
            u64 o2 = __shfl_xor_sync(0xFFFFFFFFu, key, 2); if (o2 > key) key = o2;
            if (tig == 0 && key) atomicMax(&sI[r], key);
        }
    }

    if (!diag) {
#pragma unroll
        for (int nt = 0; nt < 8; nt++) {
#pragma unroll
            for (int e = 0; e < 2; e++) {
                int ci = nt * 2 + e;
                u64 key = 0ull;
                if (bJj[ci] >= 0) {
                    u32 fb = __float_as_uint(bVj[ci]);
                    u32 s = (fb & 0x80000000u) ? ~fb : (fb | 0x80000000u);
                    key = ((u64)s << 32) | (u64)(0xFFFFFFFFu - (u32)bJj[ci]);
                }
                u64 o;
                o = __shfl_xor_sync(0xFFFFFFFFu, key, 4);  if (o > key) key = o;
                o = __shfl_xor_sync(0xFFFFFFFFu, key, 8);  if (o > key) key = o;
                o = __shfl_xor_sync(0xFFFFFFFFu, key, 16); if (o > key) key = o;
                int n = wn + nt * 8 + 2 * tig + e;
                if (gid == 0 && key) atomicMax(&sJ[n], key);
            }
        }
    }
    __syncthreads();

    if (tid < 128) {
        u64 k = sI[tid];
        if (k) atomicMax(&g_hardkey[ib + tid], k);
    } else if (!diag) {
        int u = tid - 128;
        u64 k = sJ[u];
        if (k) atomicMax(&g_hardkey[jb + u], k);
    }
}

// ---------------- K4: per-row rand dot + infoNCE + deterministic fixed-point accumulate ---
__global__ void __launch_bounds__(128) k_rowfinal(const float* __restrict__ outs) {
    int i = blockIdx.x, tid = threadIdx.x;
    int r = g_rand[i];
    u64 hk = g_hardkey[i];
    int hidx = (int)(0xFFFFFFFFu - (u32)(hk & 0xFFFFFFFFu));
    // recover v = sq[h] - 2*dot(x_i,x_h) from the sortable key
    u32 s = (u32)(hk >> 32);
    u32 fb = (s & 0x80000000u) ? (s & 0x7FFFFFFFu) : ~s;
    float vh = __uint_as_float(fb);
    float nh = 0.5f * (g_sq[hidx] - vh);

    const float* xi = outs + (size_t)i * CN;
    const float* xr = outs + (size_t)r * CN;
    float nr = 0.f;
    for (int c = tid; c < CN; c += 128) nr += xi[c] * xr[c];
    __shared__ float s0[128];
    s0[tid] = nr; __syncthreads();
    for (int st = 64; st > 0; st >>= 1) {
        if (tid < st) s0[tid] += s0[tid + st];
        __syncthreads();
    }
    if (tid == 0) {
        float l0 = g_pos[i], l1 = s0[0], l2 = nh;
        float m = fmaxf(l0, fmaxf(l1, l2));
        float lse3 = m + logf(expf(l0 - m) + expf(l1 - m) + expf(l2 - m));
        float info = lse3 - l0;
        float term = g_ce[i] + 0.1f * info;
        long long q = (long long)rint((double)term * 1073741824.0);  // 2^30 fixed point
        atomicAdd(&g_acc, (u64)q);
    }
}

// ---------------- K5: finalize ----------------
__global__ void k_final(float* __restrict__ out, int out_size) {
    double ssum = (double)(long long)g_acc / 1073741824.0;
    float loss = (float)(ssum / (double)BN);
    for (int i = threadIdx.x; i < out_size; i += 32) out[i] = loss;
}

// ---------------- launch ----------------
extern "C" void kernel_launch(void* const* d_in, const int* in_sizes, int n_in,
                              void* d_out, int out_size) {
    const float* outs    = (const float*)d_in[0];
    const float* centers = (const float*)d_in[1];
    const int*   label   = (const int*)d_in[2];
    float* out = (float*)d_out;

    cudaFuncSetAttribute(k_hard_mma, cudaFuncAttributeMaxDynamicSharedMemorySize, HARD_SMEM);

    k_rowstats<<<BN, 256>>>(outs, centers, label);
    k_hard_mma<<<GRID_TOTAL, 256, HARD_SMEM>>>(label);
    k_rowfinal<<<BN, 128>>>(outs);
    k_final<<<1, 32>>>(out, out_size);
}

// round 14
// speedup vs baseline: 1.1674x; 1.1674x over previous
#include <cuda_runtime.h>
#include <cuda_bf16.h>
#include <stdint.h>

// Problem constants
#define BN 4096
#define CN 1024

typedef unsigned long long u64;
typedef unsigned int u32;

// ---------------- device scratch (no allocations allowed) ----------------
__device__ float g_sq[BN];     // ||x_i||^2
__device__ float g_ce[BN];     // lse_i - x[i,label_i]
__device__ float g_pos[BN];    // dot(x_i, centers[label_i])
__device__ int   g_rand[BN];   // random-negative index
__device__ u64   g_hardkey[BN];// argmax key for hard negative
__device__ u64   g_acc;        // fixed-point (2^30) sum of ce_i + 0.1*info_i
__device__ __nv_bfloat16 g_hi[BN * CN];  // bf16 hi split of outs
__device__ __nv_bfloat16 g_lo[BN * CN];  // bf16 lo split of outs

// ---------------- helpers ----------------
__device__ __forceinline__ uint32_t smem_to_u32(const void* p) {
    uint32_t a;
    asm("{ .reg .u64 t; cvta.to.shared.u64 t, %1; cvt.u32.u64 %0, t; }" : "=r"(a) : "l"(p));
    return a;
}
// 64-byte-row swizzle: XOR 16B-slot bits [5:4] with row bits ((o>>7)&3)
#define SWZ64(o) ((u32)(o) ^ ((((u32)(o)) >> 3) & 0x30u))

__device__ __forceinline__ void ldsm_x4(uint32_t* r, uint32_t addr) {
    asm volatile("ldmatrix.sync.aligned.m8n8.x4.shared.b16 {%0,%1,%2,%3}, [%4];"
        : "=r"(r[0]), "=r"(r[1]), "=r"(r[2]), "=r"(r[3]) : "r"(addr));
}
__device__ __forceinline__ void mma_bf16(float* d, const uint32_t* a, const uint32_t* b) {
    asm volatile("mma.sync.aligned.m16n8k16.row.col.f32.bf16.bf16.f32 "
        "{%0,%1,%2,%3}, {%4,%5,%6,%7}, {%8,%9}, {%0,%1,%2,%3};"
        : "+f"(d[0]), "+f"(d[1]), "+f"(d[2]), "+f"(d[3])
        : "r"(a[0]), "r"(a[1]), "r"(a[2]), "r"(a[3]), "r"(b[0]), "r"(b[1]));
}
__device__ __forceinline__ void cp_async16(uint32_t saddr, const void* g) {
    asm volatile("cp.async.cg.shared.global [%0], [%1], 16;" :: "r"(saddr), "l"(g));
}
#define CP_COMMIT() asm volatile("cp.async.commit_group;" ::: "memory")
#define CP_WAIT1()  asm volatile("cp.async.wait_group 1;" ::: "memory")
#define CP_WAIT0()  asm volatile("cp.async.wait_group 0;" ::: "memory")

// ---------------- threefry2x32 (jax key 42) ----------------
__device__ __forceinline__ void threefry2x32(u32 x0, u32 x1, u32& o0, u32& o1) {
    const u32 ks0 = 0u, ks1 = 42u, ks2 = 0x1BD11BF0u;
    x0 += ks0; x1 += ks1;
#define TFR(r) { x0 += x1; x1 = (x1 << (r)) | (x1 >> (32 - (r))); x1 ^= x0; }
#define TFG0 TFR(13) TFR(15) TFR(26) TFR(6)
#define TFG1 TFR(17) TFR(29) TFR(16) TFR(24)
    TFG0; x0 += ks1; x1 += ks2 + 1u;
    TFG1; x0 += ks2; x1 += ks0 + 2u;
    TFG0; x0 += ks0; x1 += ks1 + 3u;
    TFG1; x0 += ks1; x1 += ks2 + 4u;
    TFG0; x0 += ks2; x1 += ks0 + 5u;
#undef TFR
#undef TFG0
#undef TFG1
    o0 = x0; o1 = x1;
}

// ---------------- K1: per-row stats + bf16 split + init + FUSED rand ----------------
// Blocks i < BN/2 additionally compute the random negative for rows (i, i+BN/2).
__global__ void __launch_bounds__(256) k_rowstats(
    const float* __restrict__ outs,
    const float* __restrict__ centers,
    const int*   __restrict__ label)
{
    int i = blockIdx.x;
    int tid = threadIdx.x;
    int lane = tid & 31, wid = tid >> 5;
    int lab = label[i];
    if (tid == 0) {
        g_hardkey[i] = 0ull;
        if (i == 0) g_acc = 0ull;
    }

    __shared__ float s_xlab;
    __shared__ float wmax[8], wsq[8], wpos[8], wse[8];
    __shared__ u64 sb0[256], sb1[256];

    float4 x = ((const float4*)(outs + (size_t)i * CN))[tid];
    float4 cc = ((const float4*)(centers + (size_t)lab * CN))[tid];
    float xs[4] = {x.x, x.y, x.z, x.w};
    float cs[4] = {cc.x, cc.y, cc.z, cc.w};
    int c0 = tid * 4;

    float mx = -1e30f, sq = 0.f, pos = 0.f;
    unsigned short h[4], l[4];
#pragma unroll
    for (int k = 0; k < 4; k++) {
        float v = xs[k];
        mx = fmaxf(mx, v);
        sq += v * v;
        pos += v * cs[k];
        if (c0 + k == lab) s_xlab = v;
        __nv_bfloat16 hb = __float2bfloat16(v);
        float hf = __bfloat162float(hb);
        __nv_bfloat16 lb = __float2bfloat16(v - hf);
        h[k] = *reinterpret_cast<unsigned short*>(&hb);
        l[k] = *reinterpret_cast<unsigned short*>(&lb);
    }
    uint2 hv, lv;
    hv.x = (u32)h[0] | ((u32)h[1] << 16); hv.y = (u32)h[2] | ((u32)h[3] << 16);
    lv.x = (u32)l[0] | ((u32)l[1] << 16); lv.y = (u32)l[2] | ((u32)l[3] << 16);
    size_t vidx = ((size_t)i * CN) / 4 + tid;
    ((uint2*)g_hi)[vidx] = hv;
    ((uint2*)g_lo)[vidx] = lv;

    // phase 1: warp-shuffle reduce (max, sq, pos) together
#pragma unroll
    for (int off = 16; off > 0; off >>= 1) {
        mx  = fmaxf(mx, __shfl_xor_sync(0xFFFFFFFFu, mx, off));
        sq  += __shfl_xor_sync(0xFFFFFFFFu, sq, off);
        pos += __shfl_xor_sync(0xFFFFFFFFu, pos, off);
    }
    if (lane == 0) { wmax[wid] = mx; wsq[wid] = sq; wpos[wid] = pos; }
    __syncthreads();
    float rmax = wmax[0];
#pragma unroll
    for (int k = 1; k < 8; k++) rmax = fmaxf(rmax, wmax[k]);

    // phase 2: exp-sum
    float se = expf(xs[0] - rmax) + expf(xs[1] - rmax) + expf(xs[2] - rmax) + expf(xs[3] - rmax);
#pragma unroll
    for (int off = 16; off > 0; off >>= 1) se += __shfl_xor_sync(0xFFFFFFFFu, se, off);
    if (lane == 0) wse[wid] = se;
    __syncthreads();

    if (tid == 0) {
        float tse = 0.f, tsq = 0.f, tpos = 0.f;
#pragma unroll
        for (int k = 0; k < 8; k++) { tse += wse[k]; tsq += wsq[k]; tpos += wpos[k]; }
        g_sq[i]  = tsq;
        g_pos[i] = tpos;
        g_ce[i]  = rmax + logf(tse) - s_xlab;
    }

    // ---- fused random-negative selection (pairs i and i+2048 share threefry bits) ----
    if (i < BN / 2) {
        int i1 = i + BN / 2;
        int li0 = lab;
        int li1 = label[i1];
        const u32 HALF = 8388608u;   // (4096*4096)/2
        u64 best0 = 0ull, best1 = 0ull;
        u32 base = (u32)i << 12;
        for (int j = tid; j < BN; j += 256) {
            u32 idx = base | (u32)j;
            u32 o0, o1;
            threefry2x32(idx, idx + HALF, o0, o1);
            int lj = label[j];
            u64 tie = (u64)(0xFFFFFFFFu - (u32)j);
            if (lj != li0) {
                u64 key = ((u64)(o0 >> 9) << 32) | tie;
                if (key > best0) best0 = key;
            }
            if (lj != li1) {
                u64 key = ((u64)(o1 >> 9) << 32) | tie;
                if (key > best1) best1 = key;
            }
        }
        sb0[tid] = best0; sb1[tid] = best1; __syncthreads();
        for (int s = 128; s > 0; s >>= 1) {
            if (tid < s) {
                u64 a = sb0[tid + s]; if (a > sb0[tid]) sb0[tid] = a;
                u64 b = sb1[tid + s]; if (b > sb1[tid]) sb1[tid] = b;
            }
            __syncthreads();
        }
        if (tid == 0) {
            g_rand[i]  = (int)(0xFFFFFFFFu - (u32)(sb0[0] & 0xFFFFFFFFu));
            g_rand[i1] = (int)(0xFFFFFFFFu - (u32)(sb1[0] & 0xFFFFFFFFu));
        }
    }
}

// ---------------- K3: split-bf16 mma.sync GEMM + symmetric fused masked argmax ----------
#define KC 32
#define NCHUNK_M (CN / KC)      // 32
#define STAGE_SZ 32768
#define NSTAGE 3
#define OFF_AHI 0
#define OFF_ALO 8192
#define OFF_BHI 16384
#define OFF_BLO 24576
#define OFF_SI  (NSTAGE * STAGE_SZ)     // 98304
#define OFF_SJ  (OFF_SI + 1024)
#define OFF_LA  (OFF_SJ + 1024)
#define OFF_LB  (OFF_LA + 512)
#define OFF_QA  (OFF_LB + 512)
#define OFF_QB  (OFF_QA + 512)
#define HARD_SMEM (OFF_QB + 512)        // 102400

__device__ __forceinline__ void prefetch_chunk(uint32_t smem_base, int slot, int c,
                                               int ib, int jb, bool diag, int tid) {
    uint32_t sb = smem_base + (u32)slot * STAGE_SZ;
    int k0 = c * KC;
#pragma unroll
    for (int it = 0; it < 2; it++) {
        int v = tid + it * 256;
        int row = v >> 2, cv = v & 3;
        uint32_t so = SWZ64(row * 64 + cv * 16);
        size_t ga = (size_t)(ib + row) * CN + k0 + cv * 8;
        cp_async16(sb + OFF_AHI + so, g_hi + ga);
        cp_async16(sb + OFF_ALO + so, g_lo + ga);
        if (!diag) {
            size_t gb = (size_t)(jb + row) * CN + k0 + cv * 8;
            cp_async16(sb + OFF_BHI + so, g_hi + gb);
            cp_async16(sb + OFF_BLO + so, g_lo + gb);
        }
    }
    CP_COMMIT();
}

__global__ void __launch_bounds__(256, 2) k_hard_mma(const int* __restrict__ label)
{
    extern __shared__ char sm[];
    uint32_t smem_base = smem_to_u32(sm);
    int tid = threadIdx.x;

    // triangular decode: t -> (bi, bj), bj <= bi
    int t = blockIdx.x;
    int bi = (int)((sqrtf(8.0f * (float)t + 1.0f) - 1.0f) * 0.5f);
    while ((bi + 1) * (bi + 2) / 2 <= t) bi++;
    while (bi * (bi + 1) / 2 > t) bi--;
    int bj = t - bi * (bi + 1) / 2;
    int ib = bi * 128, jb = bj * 128;
    bool diag = (bi == bj);
    uint32_t bhiOff = diag ? OFF_AHI : OFF_BHI;
    uint32_t bloOff = diag ? OFF_ALO : OFF_BLO;

    u64* sI = (u64*)(sm + OFF_SI);
    u64* sJ = (u64*)(sm + OFF_SJ);
    int* labA = (int*)(sm + OFF_LA);
    int* labB = (int*)(sm + OFF_LB);
    float* sqA = (float*)(sm + OFF_QA);
    float* sqB = (float*)(sm + OFF_QB);
    if (tid < 128) {
        sI[tid] = 0ull; sJ[tid] = 0ull;
        labA[tid] = label[ib + tid]; sqA[tid] = g_sq[ib + tid];
    } else {
        int u = tid - 128;
        labB[u] = label[jb + u]; sqB[u] = g_sq[jb + u];
    }

    // prologue: stages 0,1
    prefetch_chunk(smem_base, 0, 0, ib, jb, diag, tid);
    prefetch_chunk(smem_base, 1, 1, ib, jb, diag, tid);

    // warp/lane geometry
    int lane = tid & 31, w = tid >> 5;
    int gid = lane >> 2, tig = lane & 3;
    int wm = (w >> 1) * 32;       // 4 warps along m
    int wn = (w & 1) * 64;        // 2 warps along n
    int q  = lane >> 3, i5 = lane & 7;
    int a_r  = i5 + (q & 1) * 8;
    int a_ch = (q >> 1) * 8;
    int b_r  = i5 + (q >> 1) * 8;
    int b_ch = (q & 1) * 8;

    float acc[2][8][4];
#pragma unroll
    for (int m = 0; m < 2; m++)
#pragma unroll
        for (int n = 0; n < 8; n++)
#pragma unroll
            for (int e = 0; e < 4; e++) acc[m][n][e] = 0.f;

    int slot = 0;
    for (int c = 0; c < NCHUNK_M; c++) {
        if (c + 1 < NCHUNK_M) { CP_WAIT1(); } else { CP_WAIT0(); }
        __syncthreads();
        if (c + 2 < NCHUNK_M) {
            int ns = slot + 2; if (ns >= NSTAGE) ns -= NSTAGE;
            prefetch_chunk(smem_base, ns, c + 2, ib, jb, diag, tid);
        }
        uint32_t sb = smem_base + (u32)slot * STAGE_SZ;

#pragma unroll
        for (int ks = 0; ks < 2; ks++) {
            int kc = ks * 16;
            uint32_t ah[2][4], al[2][4];
#pragma unroll
            for (int mt = 0; mt < 2; mt++) {
                uint32_t off = SWZ64((wm + mt * 16 + a_r) * 64 + (kc + a_ch) * 2);
                ldsm_x4(ah[mt], sb + OFF_AHI + off);
                ldsm_x4(al[mt], sb + OFF_ALO + off);
            }
#pragma unroll
            for (int bb = 0; bb < 4; bb++) {
                uint32_t bh[4], bl[4];
                uint32_t off = SWZ64((wn + bb * 16 + b_r) * 64 + (kc + b_ch) * 2);
                ldsm_x4(bh, sb + bhiOff + off);
                ldsm_x4(bl, sb + bloOff + off);
#pragma unroll
                for (int mt = 0; mt < 2; mt++) {
                    mma_bf16(acc[mt][bb * 2],     ah[mt], bh);
                    mma_bf16(acc[mt][bb * 2 + 1], ah[mt], bh + 2);
                    mma_bf16(acc[mt][bb * 2],     ah[mt], bl);
                    mma_bf16(acc[mt][bb * 2 + 1], ah[mt], bl + 2);
                    mma_bf16(acc[mt][bb * 2],     al[mt], bh);
                    mma_bf16(acc[mt][bb * 2 + 1], al[mt], bh + 2);
                }
            }
        }
        slot++; if (slot >= NSTAGE) slot = 0;
    }

    // ---- epilogue: masked argmax, both directions ----
    float bVj[16]; int bJj[16];
#pragma unroll
    for (int x = 0; x < 16; x++) { bVj[x] = -1e38f; bJj[x] = -1; }

#pragma unroll
    for (int mt = 0; mt < 2; mt++) {
#pragma unroll
        for (int h = 0; h < 2; h++) {
            int r = wm + mt * 16 + gid + h * 8;
            int labr = labA[r];
            float sqa = sqA[r];
            float bVi = -1e38f; int bJi = -1;
#pragma unroll
            for (int nt = 0; nt < 8; nt++) {
#pragma unroll
                for (int e = 0; e < 2; e++) {
                    int n = wn + nt * 8 + 2 * tig + e;
                    if (labB[n] != labr) {
                        float m2d = -2.0f * acc[mt][nt][h * 2 + e];
                        float vi = sqB[n] + m2d;
                        int jg = jb + n;
                        if (vi > bVi || (vi == bVi && jg < bJi)) { bVi = vi; bJi = jg; }
                        int ci = nt * 2 + e;
                        float vj = sqa + m2d;
                        int jg2 = ib + r;
                        if (vj > bVj[ci] || (vj == bVj[ci] && jg2 < bJj[ci])) { bVj[ci] = vj; bJj[ci] = jg2; }
                    }
                }
            }
            u64 key = 0ull;
            if (bJi >= 0) {
                u32 fb = __float_as_uint(bVi);
                u32 s = (fb & 0x80000000u) ? ~fb : (fb | 0x80000000u);
                key = ((u64)s << 32) | (u64)(0xFFFFFFFFu - (u32)bJi);
            }
            u64 o1 = __shfl_xor_sync(0xFFFFFFFFu, key, 1); if (o1 > key) key = o1;
            u64 o2 = __shfl_xor_sync(0xFFFFFFFFu, key, 2); if (o2 > key) key = o2;
            if (tig == 0 && key) atomicMax(&sI[r], key);
        }
    }

    if (!diag) {
#pragma unroll
        for (int nt = 0; nt < 8; nt++) {
#pragma unroll
            for (int e = 0; e < 2; e++) {
                int ci = nt * 2 + e;
                u64 key = 0ull;
                if (bJj[ci] >= 0) {
                    u32 fb = __float_as_uint(bVj[ci]);
                    u32 s = (fb & 0x80000000u) ? ~fb : (fb | 0x80000000u);
                    key = ((u64)s << 32) | (u64)(0xFFFFFFFFu - (u32)bJj[ci]);
                }
                u64 o;
                o = __shfl_xor_sync(0xFFFFFFFFu, key, 4);  if (o > key) key = o;
                o = __shfl_xor_sync(0xFFFFFFFFu, key, 8);  if (o > key) key = o;
                o = __shfl_xor_sync(0xFFFFFFFFu, key, 16); if (o > key) key = o;
                int n = wn + nt * 8 + 2 * tig + e;
                if (gid == 0 && key) atomicMax(&sJ[n], key);
            }
        }
    }
    __syncthreads();

    if (tid < 128) {
        u64 k = sI[tid];
        if (k) atomicMax(&g_hardkey[ib + tid], k);
    } else if (!diag) {
        int u = tid - 128;
        u64 k = sJ[u];
        if (k) atomicMax(&g_hardkey[jb + u], k);
    }
}

// ---------------- K4: per-row rand dot + infoNCE + deterministic fixed-point accumulate ---
__global__ void __launch_bounds__(128) k_rowfinal(const float* __restrict__ outs) {
    int i = blockIdx.x, tid = threadIdx.x;
    int r = g_rand[i];
    u64 hk = g_hardkey[i];
    int hidx = (int)(0xFFFFFFFFu - (u32)(hk & 0xFFFFFFFFu));
    // recover v = sq[h] - 2*dot(x_i,x_h) from the sortable key
    u32 s = (u32)(hk >> 32);
    u32 fb = (s & 0x80000000u) ? (s & 0x7FFFFFFFu) : ~s;
    float vh = __uint_as_float(fb);
    float nh = 0.5f * (g_sq[hidx] - vh);

    const float* xi = outs + (size_t)i * CN;
    const float* xr = outs + (size_t)r * CN;
    float nr = 0.f;
    for (int c = tid; c < CN; c += 128) nr += xi[c] * xr[c];
#pragma unroll
    for (int off = 16; off > 0; off >>= 1) nr += __shfl_xor_sync(0xFFFFFFFFu, nr, off);
    __shared__ float s0[4];
    if ((tid & 31) == 0) s0[tid >> 5] = nr;
    __syncthreads();
    if (tid == 0) {
        float l1 = s0[0] + s0[1] + s0[2] + s0[3];
        float l0 = g_pos[i], l2 = nh;
        float m = fmaxf(l0, fmaxf(l1, l2));
        float lse3 = m + logf(expf(l0 - m) + expf(l1 - m) + expf(l2 - m));
        float info = lse3 - l0;
        float term = g_ce[i] + 0.1f * info;
        long long q = (long long)rint((double)term * 1073741824.0);  // 2^30 fixed point
        atomicAdd(&g_acc, (u64)q);
    }
}

// ---------------- K5: finalize ----------------
__global__ void k_final(float* __restrict__ out, int out_size) {
    double ssum = (double)(long long)g_acc / 1073741824.0;
    float loss = (float)(ssum / (double)BN);
    for (int i = threadIdx.x; i < out_size; i += 32) out[i] = loss;
}

// ---------------- launch ----------------
extern "C" void kernel_launch(void* const* d_in, const int* in_sizes, int n_in,
                              void* d_out, int out_size) {
    const float* outs    = (const float*)d_in[0];
    const float* centers = (const float*)d_in[1];
    const int*   label   = (const int*)d_in[2];
    float* out = (float*)d_out;

    cudaFuncSetAttribute(k_hard_mma, cudaFuncAttributeMaxDynamicSharedMemorySize, HARD_SMEM);

    k_rowstats<<<BN, 256>>>(outs, centers, label);
    int ntiles = (BN / 128) * (BN / 128 + 1) / 2;  // 528
    k_hard_mma<<<ntiles, 256, HARD_SMEM>>>(label);
    k_rowfinal<<<BN, 128>>>(outs);
    k_final<<<1, 32>>>(out, out_size);
}

// round 16
// speedup vs baseline: 1.9230x; 1.6472x over previous
#include <cuda_runtime.h>
#include <cuda_bf16.h>
#include <stdint.h>

// Problem constants
#define BN 4096
#define CN 1024

typedef unsigned long long u64;
typedef unsigned int u32;

// ---------------- device scratch (no allocations allowed) ----------------
__device__ float g_sq[BN];     // ||x_i||^2
__device__ float g_ce[BN];     // lse_i - x[i,label_i]
__device__ float g_pos[BN];    // dot(x_i, centers[label_i])
__device__ int   g_rand[BN];   // random-negative index
__device__ u64   g_hardkey[BN];// argmax key for hard negative
__device__ u64   g_acc;        // fixed-point (2^30) sum of ce_i + 0.1*info_i
__device__ __nv_bfloat16 g_hi[BN * CN];  // bf16 of outs

// ---------------- helpers ----------------
__device__ __forceinline__ uint32_t smem_to_u32(const void* p) {
    uint32_t a;
    asm("{ .reg .u64 t; cvta.to.shared.u64 t, %1; cvt.u32.u64 %0, t; }" : "=r"(a) : "l"(p));
    return a;
}
// 64-byte-row swizzle: XOR 16B-slot bits [5:4] with row bits ((o>>7)&3)
#define SWZ64(o) ((u32)(o) ^ ((((u32)(o)) >> 3) & 0x30u))

__device__ __forceinline__ void ldsm_x4(uint32_t* r, uint32_t addr) {
    asm volatile("ldmatrix.sync.aligned.m8n8.x4.shared.b16 {%0,%1,%2,%3}, [%4];"
        : "=r"(r[0]), "=r"(r[1]), "=r"(r[2]), "=r"(r[3]) : "r"(addr));
}
__device__ __forceinline__ void mma_bf16(float* d, const uint32_t* a, const uint32_t* b) {
    asm volatile("mma.sync.aligned.m16n8k16.row.col.f32.bf16.bf16.f32 "
        "{%0,%1,%2,%3}, {%4,%5,%6,%7}, {%8,%9}, {%0,%1,%2,%3};"
        : "+f"(d[0]), "+f"(d[1]), "+f"(d[2]), "+f"(d[3])
        : "r"(a[0]), "r"(a[1]), "r"(a[2]), "r"(a[3]), "r"(b[0]), "r"(b[1]));
}
__device__ __forceinline__ void cp_async16(uint32_t saddr, const void* g) {
    asm volatile("cp.async.cg.shared.global [%0], [%1], 16;" :: "r"(saddr), "l"(g));
}
#define CP_COMMIT() asm volatile("cp.async.commit_group;" ::: "memory")
#define CP_WAIT2()  asm volatile("cp.async.wait_group 2;" ::: "memory")
#define CP_WAIT1()  asm volatile("cp.async.wait_group 1;" ::: "memory")
#define CP_WAIT0()  asm volatile("cp.async.wait_group 0;" ::: "memory")

// ---------------- threefry2x32 (jax key 42) ----------------
__device__ __forceinline__ void threefry2x32(u32 x0, u32 x1, u32& o0, u32& o1) {
    const u32 ks0 = 0u, ks1 = 42u, ks2 = 0x1BD11BF0u;
    x0 += ks0; x1 += ks1;
#define TFR(r) { x0 += x1; x1 = (x1 << (r)) | (x1 >> (32 - (r))); x1 ^= x0; }
#define TFG0 TFR(13) TFR(15) TFR(26) TFR(6)
#define TFG1 TFR(17) TFR(29) TFR(16) TFR(24)
    TFG0; x0 += ks1; x1 += ks2 + 1u;
    TFG1; x0 += ks2; x1 += ks0 + 2u;
    TFG0; x0 += ks0; x1 += ks1 + 3u;
    TFG1; x0 += ks1; x1 += ks2 + 4u;
    TFG0; x0 += ks2; x1 += ks0 + 5u;
#undef TFR
#undef TFG0
#undef TFG1
    o0 = x0; o1 = x1;
}

// ---------------- K1: per-row stats + bf16 cast + init + FUSED rand ----------------
__global__ void __launch_bounds__(256) k_rowstats(
    const float* __restrict__ outs,
    const float* __restrict__ centers,
    const int*   __restrict__ label)
{
    int i = blockIdx.x;
    int tid = threadIdx.x;
    int lane = tid & 31, wid = tid >> 5;
    int lab = label[i];
    if (tid == 0) {
        g_hardkey[i] = 0ull;
        if (i == 0) g_acc = 0ull;
    }

    __shared__ float s_xlab;
    __shared__ float wmax[8], wsq[8], wpos[8], wse[8];
    __shared__ u64 sb0[256], sb1[256];

    float4 x = ((const float4*)(outs + (size_t)i * CN))[tid];
    float4 cc = ((const float4*)(centers + (size_t)lab * CN))[tid];
    float xs[4] = {x.x, x.y, x.z, x.w};
    float cs[4] = {cc.x, cc.y, cc.z, cc.w};
    int c0 = tid * 4;

    float mx = -1e30f, sq = 0.f, pos = 0.f;
    unsigned short h[4];
#pragma unroll
    for (int k = 0; k < 4; k++) {
        float v = xs[k];
        mx = fmaxf(mx, v);
        sq += v * v;
        pos += v * cs[k];
        if (c0 + k == lab) s_xlab = v;
        __nv_bfloat16 hb = __float2bfloat16(v);
        h[k] = *reinterpret_cast<unsigned short*>(&hb);
    }
    uint2 hv;
    hv.x = (u32)h[0] | ((u32)h[1] << 16); hv.y = (u32)h[2] | ((u32)h[3] << 16);
    size_t vidx = ((size_t)i * CN) / 4 + tid;
    ((uint2*)g_hi)[vidx] = hv;

    // phase 1: warp-shuffle reduce (max, sq, pos) together
#pragma unroll
    for (int off = 16; off > 0; off >>= 1) {
        mx  = fmaxf(mx, __shfl_xor_sync(0xFFFFFFFFu, mx, off));
        sq  += __shfl_xor_sync(0xFFFFFFFFu, sq, off);
        pos += __shfl_xor_sync(0xFFFFFFFFu, pos, off);
    }
    if (lane == 0) { wmax[wid] = mx; wsq[wid] = sq; wpos[wid] = pos; }
    __syncthreads();
    float rmax = wmax[0];
#pragma unroll
    for (int k = 1; k < 8; k++) rmax = fmaxf(rmax, wmax[k]);

    // phase 2: exp-sum
    float se = expf(xs[0] - rmax) + expf(xs[1] - rmax) + expf(xs[2] - rmax) + expf(xs[3] - rmax);
#pragma unroll
    for (int off = 16; off > 0; off >>= 1) se += __shfl_xor_sync(0xFFFFFFFFu, se, off);
    if (lane == 0) wse[wid] = se;
    __syncthreads();

    if (tid == 0) {
        float tse = 0.f, tsq = 0.f, tpos = 0.f;
#pragma unroll
        for (int k = 0; k < 8; k++) { tse += wse[k]; tsq += wsq[k]; tpos += wpos[k]; }
        g_sq[i]  = tsq;
        g_pos[i] = tpos;
        g_ce[i]  = rmax + logf(tse) - s_xlab;
    }

    // ---- fused random-negative selection (pairs i and i+2048 share threefry bits) ----
    if (i < BN / 2) {
        int i1 = i + BN / 2;
        int li0 = lab;
        int li1 = label[i1];
        const u32 HALF = 8388608u;   // (4096*4096)/2
        u64 best0 = 0ull, best1 = 0ull;
        u32 base = (u32)i << 12;
        for (int j = tid; j < BN; j += 256) {
            u32 idx = base | (u32)j;
            u32 o0, o1;
            threefry2x32(idx, idx + HALF, o0, o1);
            int lj = label[j];
            u64 tie = (u64)(0xFFFFFFFFu - (u32)j);
            if (lj != li0) {
                u64 key = ((u64)(o0 >> 9) << 32) | tie;
                if (key > best0) best0 = key;
            }
            if (lj != li1) {
                u64 key = ((u64)(o1 >> 9) << 32) | tie;
                if (key > best1) best1 = key;
            }
        }
        sb0[tid] = best0; sb1[tid] = best1; __syncthreads();
        for (int s = 128; s > 0; s >>= 1) {
            if (tid < s) {
                u64 a = sb0[tid + s]; if (a > sb0[tid]) sb0[tid] = a;
                u64 b = sb1[tid + s]; if (b > sb1[tid]) sb1[tid] = b;
            }
            __syncthreads();
        }
        if (tid == 0) {
            g_rand[i]  = (int)(0xFFFFFFFFu - (u32)(sb0[0] & 0xFFFFFFFFu));
            g_rand[i1] = (int)(0xFFFFFFFFu - (u32)(sb1[0] & 0xFFFFFFFFu));
        }
    }
}

// ---------------- K3: single-pass bf16 mma.sync GEMM + symmetric fused masked argmax -----
// Hard-negative selection tolerates bf16 noise: flips occur only between near-ties in v,
// and the hard logit sits ~100 below the softmax max (exp-suppressed), so the loss is
// insensitive. 4-stage cp.async ring, 16 KB/stage, 2 CTAs/SM.
#define KC 32
#define NCHUNK_M (CN / KC)      // 32
#define STAGE_SZ 16384
#define NSTAGE 4
#define OFF_AHI 0
#define OFF_BHI 8192
#define OFF_SI  (NSTAGE * STAGE_SZ)     // 65536
#define OFF_SJ  (OFF_SI + 1024)
#define OFF_LA  (OFF_SJ + 1024)
#define OFF_LB  (OFF_LA + 512)
#define OFF_QA  (OFF_LB + 512)
#define OFF_QB  (OFF_QA + 512)
#define HARD_SMEM (OFF_QB + 512)        // 69632

__device__ __forceinline__ void prefetch_chunk(uint32_t smem_base, int slot, int c,
                                               int ib, int jb, bool diag, int tid) {
    uint32_t sb = smem_base + (u32)slot * STAGE_SZ;
    int k0 = c * KC;
#pragma unroll
    for (int it = 0; it < 2; it++) {
        int v = tid + it * 256;          // 0..511
        int row = v >> 2, cv = v & 3;
        uint32_t so = SWZ64(row * 64 + cv * 16);
        size_t ga = (size_t)(ib + row) * CN + k0 + cv * 8;
        cp_async16(sb + OFF_AHI + so, g_hi + ga);
        if (!diag) {
            size_t gb = (size_t)(jb + row) * CN + k0 + cv * 8;
            cp_async16(sb + OFF_BHI + so, g_hi + gb);
        }
    }
    CP_COMMIT();
}

__global__ void __launch_bounds__(256, 2) k_hard_mma(const int* __restrict__ label)
{
    extern __shared__ char sm[];
    uint32_t smem_base = smem_to_u32(sm);
    int tid = threadIdx.x;

    // triangular decode: t -> (bi, bj), bj <= bi
    int t = blockIdx.x;
    int bi = (int)((sqrtf(8.0f * (float)t + 1.0f) - 1.0f) * 0.5f);
    while ((bi + 1) * (bi + 2) / 2 <= t) bi++;
    while (bi * (bi + 1) / 2 > t) bi--;
    int bj = t - bi * (bi + 1) / 2;
    int ib = bi * 128, jb = bj * 128;
    bool diag = (bi == bj);
    uint32_t bhiOff = diag ? OFF_AHI : OFF_BHI;

    u64* sI = (u64*)(sm + OFF_SI);
    u64* sJ = (u64*)(sm + OFF_SJ);
    int* labA = (int*)(sm + OFF_LA);
    int* labB = (int*)(sm + OFF_LB);
    float* sqA = (float*)(sm + OFF_QA);
    float* sqB = (float*)(sm + OFF_QB);
    if (tid < 128) {
        sI[tid] = 0ull; sJ[tid] = 0ull;
        labA[tid] = label[ib + tid]; sqA[tid] = g_sq[ib + tid];
    } else {
        int u = tid - 128;
        labB[u] = label[jb + u]; sqB[u] = g_sq[jb + u];
    }

    // prologue: stages 0,1,2
    prefetch_chunk(smem_base, 0, 0, ib, jb, diag, tid);
    prefetch_chunk(smem_base, 1, 1, ib, jb, diag, tid);
    prefetch_chunk(smem_base, 2, 2, ib, jb, diag, tid);

    // warp/lane geometry
    int lane = tid & 31, w = tid >> 5;
    int gid = lane >> 2, tig = lane & 3;
    int wm = (w >> 1) * 32;       // 4 warps along m
    int wn = (w & 1) * 64;        // 2 warps along n
    int q  = lane >> 3, i5 = lane & 7;
    int a_r  = i5 + (q & 1) * 8;
    int a_ch = (q >> 1) * 8;
    int b_r  = i5 + (q >> 1) * 8;
    int b_ch = (q & 1) * 8;

    float acc[2][8][4];
#pragma unroll
    for (int m = 0; m < 2; m++)
#pragma unroll
        for (int n = 0; n < 8; n++)
#pragma unroll
            for (int e = 0; e < 4; e++) acc[m][n][e] = 0.f;

    for (int c = 0; c < NCHUNK_M; c++) {
        if (c + 3 <= NCHUNK_M) { CP_WAIT2(); }
        else if (c + 2 == NCHUNK_M) { CP_WAIT1(); }
        else { CP_WAIT0(); }
        __syncthreads();
        if (c + 3 < NCHUNK_M) {
            prefetch_chunk(smem_base, (c + 3) & 3, c + 3, ib, jb, diag, tid);
        }
        uint32_t sb = smem_base + (u32)(c & 3) * STAGE_SZ;

#pragma unroll
        for (int ks = 0; ks < 2; ks++) {
            int kc = ks * 16;
            uint32_t ah[2][4];
#pragma unroll
            for (int mt = 0; mt < 2; mt++) {
                uint32_t off = SWZ64((wm + mt * 16 + a_r) * 64 + (kc + a_ch) * 2);
                ldsm_x4(ah[mt], sb + OFF_AHI + off);
            }
#pragma unroll
            for (int bb = 0; bb < 4; bb++) {
                uint32_t bh[4];
                uint32_t off = SWZ64((wn + bb * 16 + b_r) * 64 + (kc + b_ch) * 2);
                ldsm_x4(bh, sb + bhiOff + off);
#pragma unroll
                for (int mt = 0; mt < 2; mt++) {
                    mma_bf16(acc[mt][bb * 2],     ah[mt], bh);
                    mma_bf16(acc[mt][bb * 2 + 1], ah[mt], bh + 2);
                }
            }
        }
    }

    // ---- epilogue: masked argmax, both directions ----
    float bVj[16]; int bJj[16];
#pragma unroll
    for (int x = 0; x < 16; x++) { bVj[x] = -1e38f; bJj[x] = -1; }

#pragma unroll
    for (int mt = 0; mt < 2; mt++) {
#pragma unroll
        for (int h = 0; h < 2; h++) {
            int r = wm + mt * 16 + gid + h * 8;
            int labr = labA[r];
            float sqa = sqA[r];
            float bVi = -1e38f; int bJi = -1;
#pragma unroll
            for (int nt = 0; nt < 8; nt++) {
#pragma unroll
                for (int e = 0; e < 2; e++) {
                    int n = wn + nt * 8 + 2 * tig + e;
                    if (labB[n] != labr) {
                        float m2d = -2.0f * acc[mt][nt][h * 2 + e];
                        float vi = sqB[n] + m2d;
                        int jg = jb + n;
                        if (vi > bVi || (vi == bVi && jg < bJi)) { bVi = vi; bJi = jg; }
                        int ci = nt * 2 + e;
                        float vj = sqa + m2d;
                        int jg2 = ib + r;
                        if (vj > bVj[ci] || (vj == bVj[ci] && jg2 < bJj[ci])) { bVj[ci] = vj; bJj[ci] = jg2; }
                    }
                }
            }
            u64 key = 0ull;
            if (bJi >= 0) {
                u32 fb = __float_as_uint(bVi);
                u32 s = (fb & 0x80000000u) ? ~fb : (fb | 0x80000000u);
                key = ((u64)s << 32) | (u64)(0xFFFFFFFFu - (u32)bJi);
            }
            u64 o1 = __shfl_xor_sync(0xFFFFFFFFu, key, 1); if (o1 > key) key = o1;
            u64 o2 = __shfl_xor_sync(0xFFFFFFFFu, key, 2); if (o2 > key) key = o2;
            if (tig == 0 && key) atomicMax(&sI[r], key);
        }
    }

    if (!diag) {
#pragma unroll
        for (int nt = 0; nt < 8; nt++) {
#pragma unroll
            for (int e = 0; e < 2; e++) {
                int ci = nt * 2 + e;
                u64 key = 0ull;
                if (bJj[ci] >= 0) {
                    u32 fb = __float_as_uint(bVj[ci]);
                    u32 s = (fb & 0x80000000u) ? ~fb : (fb | 0x80000000u);
                    key = ((u64)s << 32) | (u64)(0xFFFFFFFFu - (u32)bJj[ci]);
                }
                u64 o;
                o = __shfl_xor_sync(0xFFFFFFFFu, key, 4);  if (o > key) key = o;
                o = __shfl_xor_sync(0xFFFFFFFFu, key, 8);  if (o > key) key = o;
                o = __shfl_xor_sync(0xFFFFFFFFu, key, 16); if (o > key) key = o;
                int n = wn + nt * 8 + 2 * tig + e;
                if (gid == 0 && key) atomicMax(&sJ[n], key);
            }
        }
    }
    __syncthreads();

    if (tid < 128) {
        u64 k = sI[tid];
        if (k) atomicMax(&g_hardkey[ib + tid], k);
    } else if (!diag) {
        int u = tid - 128;
        u64 k = sJ[u];
        if (k) atomicMax(&g_hardkey[jb + u], k);
    }
}

// ---------------- K4: per-row rand dot + infoNCE + deterministic fixed-point accumulate ---
__global__ void __launch_bounds__(128) k_rowfinal(const float* __restrict__ outs) {
    int i = blockIdx.x, tid = threadIdx.x;
    int r = g_rand[i];
    u64 hk = g_hardkey[i];
    int hidx = (int)(0xFFFFFFFFu - (u32)(hk & 0xFFFFFFFFu));
    // recover v = sq[h] - 2*dot(x_i,x_h) from the sortable key
    u32 s = (u32)(hk >> 32);
    u32 fb = (s & 0x80000000u) ? (s & 0x7FFFFFFFu) : ~s;
    float vh = __uint_as_float(fb);
    float nh = 0.5f * (g_sq[hidx] - vh);

    const float* xi = outs + (size_t)i * CN;
    const float* xr = outs + (size_t)r * CN;
    float nr = 0.f;
    for (int c = tid; c < CN; c += 128) nr += xi[c] * xr[c];
#pragma unroll
    for (int off = 16; off > 0; off >>= 1) nr += __shfl_xor_sync(0xFFFFFFFFu, nr, off);
    __shared__ float s0[4];
    if ((tid & 31) == 0) s0[tid >> 5] = nr;
    __syncthreads();
    if (tid == 0) {
        float l1 = s0[0] + s0[1] + s0[2] + s0[3];
        float l0 = g_pos[i], l2 = nh;
        float m = fmaxf(l0, fmaxf(l1, l2));
        float lse3 = m + logf(expf(l0 - m) + expf(l1 - m) + expf(l2 - m));
        float info = lse3 - l0;
        float term = g_ce[i] + 0.1f * info;
        long long q = (long long)rint((double)term * 1073741824.0);  // 2^30 fixed point
        atomicAdd(&g_acc, (u64)q);
    }
}

// ---------------- K5: finalize ----------------
__global__ void k_final(float* __restrict__ out, int out_size) {
    double ssum = (double)(long long)g_acc / 1073741824.0;
    float loss = (float)(ssum / (double)BN);
    for (int i = threadIdx.x; i < out_size; i += 32) out[i] = loss;
}

// ---------------- launch ----------------
extern "C" void kernel_launch(void* const* d_in, const int* in_sizes, int n_in,
                              void* d_out, int out_size) {
    const float* outs    = (const float*)d_in[0];
    const float* centers = (const float*)d_in[1];
    const int*   label   = (const int*)d_in[2];
    float* out = (float*)d_out;

    cudaFuncSetAttribute(k_hard_mma, cudaFuncAttributeMaxDynamicSharedMemorySize, HARD_SMEM);

    k_rowstats<<<BN, 256>>>(outs, centers, label);
    int ntiles = (BN / 128) * (BN / 128 + 1) / 2;  // 528
    k_hard_mma<<<ntiles, 256, HARD_SMEM>>>(label);
    k_rowfinal<<<BN, 128>>>(outs);
    k_final<<<1, 32>>>(out, out_size);
}